// round 2
// baseline (speedup 1.0000x reference)
#include <cuda_runtime.h>
#include <math.h>

#define BATCH 4
#define SEQ 1024
#define DIM 1024
#define NHEADS 16
#define HDIM 64
#define MLP 4096
#define MTOT (BATCH*SEQ)        /* 4096 */
#define QKVW (5*NHEADS*HDIM)    /* 5120 */
#define ATTN_CLIP 100.0f
#define NORM_CLIP 1000.0f
#define EPSF 1e-6f

// ---------------- scratch (static device globals: allowed) ----------------
__device__ float g_h  [MTOT*DIM];    // 16MB
__device__ float g_qkv[MTOT*QKVW];   // 80MB
__device__ float g_o  [MTOT*DIM];    // 16MB
__device__ float g_x2 [MTOT*DIM];    // 16MB
__device__ float g_h2 [MTOT*DIM];    // 16MB
__device__ float g_f  [(size_t)MTOT*MLP]; // 64MB
__device__ float g_part[BATCH*128];
__device__ float g_nx[BATCH];
__device__ float g_lam;

// ---------------- deterministic per-batch sum of squares ----------------
__global__ void reduce_sq_kernel(const float* __restrict__ x) {
    const int b = blockIdx.y, blk = blockIdx.x;
    const int N = SEQ*DIM;          // per batch
    const int per = N / 128;        // 8192 per block
    const float* p = x + (size_t)b*N + (size_t)blk*per;
    float s = 0.f;
    for (int i = threadIdx.x; i < per; i += 256) { float v = p[i]; s += v*v; }
    // block reduce
    __shared__ float red[8];
    int lane = threadIdx.x & 31, w = threadIdx.x >> 5;
#pragma unroll
    for (int o = 16; o; o >>= 1) s += __shfl_down_sync(0xffffffffu, s, o);
    if (lane == 0) red[w] = s;
    __syncthreads();
    if (w == 0) {
        s = (lane < 8) ? red[lane] : 0.f;
#pragma unroll
        for (int o = 4; o; o >>= 1) s += __shfl_down_sync(0xffffffffu, s, o);
        if (lane == 0) g_part[b*128 + blk] = s;
    }
}

__global__ void compute_nx_kernel() {
    int b = threadIdx.x;
    if (b < BATCH) {
        float s = 0.f;
        for (int i = 0; i < 128; i++) s += g_part[b*128 + i];
        s = fminf(fmaxf(s, EPSF), NORM_CLIP);
        float gx = sqrtf(s);
        float nx = gx / (gx + EPSF);        // mean over size-1 axis == identity
        nx = fminf(fmaxf(nx, -NORM_CLIP), NORM_CLIP);
        g_nx[b] = nx;
    }
}

__global__ void compute_lam_kernel(const float* __restrict__ lq1, const float* __restrict__ lk1,
                                   const float* __restrict__ lq2, const float* __restrict__ lk2) {
    float s1 = 0.f, s2 = 0.f;
    for (int d = 0; d < HDIM; d++) { s1 += lq1[d]*lk1[d]; s2 += lq2[d]*lk2[d]; }
    s1 = fminf(fmaxf(s1, -10.f), 10.f);
    s2 = fminf(fmaxf(s2, -10.f), 10.f);
    float layer_factor = fminf(fmaxf(0.0f * 0.3f, 0.f), 5.f);   // layer_idx = 0
    float lam_init = 0.8f - 0.6f*expf(-layer_factor);
    float lam = expf(s1) - expf(s2) + lam_init;
    g_lam = fminf(fmaxf(lam, 0.1f), 5.f);
}

// ---------------- GRN elementwise: out = gamma*(x*nx) + beta + x ----------------
__global__ void grn_kernel(const float* __restrict__ x, const float* __restrict__ gamma,
                           const float* __restrict__ beta, float* __restrict__ out) {
    int idx = blockIdx.x*blockDim.x + threadIdx.x;
    int e = idx * 4;
    int b = e / (SEQ*DIM);
    int d = e % DIM;
    float nx = g_nx[b];
    float4 xv = *(const float4*)(x + e);
    float4 gv = *(const float4*)(gamma + d);
    float4 bv = *(const float4*)(beta + d);
    float4 r;
    r.x = gv.x*(xv.x*nx) + bv.x + xv.x;
    r.y = gv.y*(xv.y*nx) + bv.y + xv.y;
    r.z = gv.z*(xv.z*nx) + bv.z + xv.z;
    r.w = gv.w*(xv.w*nx) + bv.w + xv.w;
    *(float4*)(out + e) = r;
}

// ---------------- SGEMM 128x128x8, 8x8 microtile, 256 threads ----------------
// EPI: 0=none, 1=+bias, 2=+bias+residual, 3=silu(+bias)
template<int EPI>
__global__ __launch_bounds__(256, 2)
void sgemm_kernel(const float* __restrict__ A, const float* __restrict__ B,
                  float* __restrict__ C, int M, int N, int K,
                  const float* __restrict__ bias, const float* __restrict__ res) {
    __shared__ float As[8][132];   // padded: avoids store-bank conflicts
    __shared__ float Bs[8][128];

    const int tid = threadIdx.x;
    const int bx = blockIdx.x, by = blockIdx.y;
    const int tx = tid & 15, ty = tid >> 4;
    const int row0 = by*128, col0 = bx*128;

    const int aRow = tid >> 1, aCol = (tid & 1) * 4;
    const int bRow = tid >> 5, bCol = (tid & 31) * 4;

    const float* Aptr = A + (size_t)(row0 + aRow)*K + aCol;
    const float* Bptr = B + (size_t)bRow*N + col0 + bCol;

    float acc[8][8];
#pragma unroll
    for (int i = 0; i < 8; i++)
#pragma unroll
        for (int j = 0; j < 8; j++) acc[i][j] = 0.f;

    for (int k0 = 0; k0 < K; k0 += 8) {
        float4 av = *(const float4*)(Aptr + k0);
        float4 bv = *(const float4*)(Bptr + (size_t)k0*N);
        As[aCol+0][aRow] = av.x;
        As[aCol+1][aRow] = av.y;
        As[aCol+2][aRow] = av.z;
        As[aCol+3][aRow] = av.w;
        *(float4*)(&Bs[bRow][bCol]) = bv;
        __syncthreads();
#pragma unroll
        for (int k = 0; k < 8; ++k) {
            float a[8], b[8];
            *(float4*)(a)   = *(const float4*)(&As[k][ty*8]);
            *(float4*)(a+4) = *(const float4*)(&As[k][ty*8+4]);
            *(float4*)(b)   = *(const float4*)(&Bs[k][tx*8]);
            *(float4*)(b+4) = *(const float4*)(&Bs[k][tx*8+4]);
#pragma unroll
            for (int i = 0; i < 8; i++)
#pragma unroll
                for (int j = 0; j < 8; j++) acc[i][j] += a[i]*b[j];
        }
        __syncthreads();
    }

    // epilogue
    float bb[8];
#pragma unroll
    for (int j = 0; j < 8; j++)
        bb[j] = (EPI >= 1) ? bias[col0 + tx*8 + j] : 0.f;

#pragma unroll
    for (int i = 0; i < 8; i++) {
        int row = row0 + ty*8 + i;
        size_t off = (size_t)row*N + col0 + tx*8;
        float v[8];
#pragma unroll
        for (int j = 0; j < 8; j++) {
            float t = acc[i][j] + bb[j];
            if (EPI == 3) t = t / (1.f + __expf(-t));   // silu
            if (EPI == 2) t += res[off + j];
            v[j] = t;
        }
        *(float4*)(C + off)     = *(float4*)(v);
        *(float4*)(C + off + 4) = *(float4*)(v + 4);
    }
}

// ---------------- fused differential flash attention ----------------
// grid = (16 q-tiles, H, B), 256 threads. Streams 1 and 2 share V tiles.
#define PITCH 65
#define SMEM_ATTN (7 * 64 * PITCH * 4)

__global__ __launch_bounds__(256)
void diff_attn_kernel(const float* __restrict__ qkv, float* __restrict__ o) {
    extern __shared__ float sm[];
    float* q1s = sm;
    float* q2s = q1s + 64*PITCH;
    float* k1s = q2s + 64*PITCH;
    float* k2s = k1s + 64*PITCH;
    float* vs  = k2s + 64*PITCH;
    float* s1  = vs  + 64*PITCH;
    float* s2  = s1  + 64*PITCH;

    const int tid = threadIdx.x;
    const int qt = blockIdx.x, h = blockIdx.y, b = blockIdx.z;
    const int q0 = qt * 64;
    const float scale = 0.125f;        // 64^-0.5
    const float lam = g_lam;

    const size_t base = ((size_t)b*SEQ)*QKVW + (size_t)h*HDIM;

    // load Q tiles (streams 1 & 2)
    for (int idx = tid; idx < 64*64; idx += 256) {
        int r = idx >> 6, c = idx & 63;
        size_t g = base + (size_t)(q0 + r)*QKVW + c;
        q1s[r*PITCH + c] = qkv[g + 0*NHEADS*HDIM];
        q2s[r*PITCH + c] = qkv[g + 1*NHEADS*HDIM];
    }

    // AV-phase ownership: row r, 16-dim slice, 16-key slice
    const int r  = tid >> 2;
    const int kg = (tid & 3) * 16;
    const int dbase = kg;
    float m1 = -1e30f, l1 = 0.f, m2 = -1e30f, l2 = 0.f;
    float o1[16], o2[16];
#pragma unroll
    for (int j = 0; j < 16; j++) { o1[j] = 0.f; o2[j] = 0.f; }

    // score-phase ownership: 4 rows x 4 keys
    const int sr0 = (tid >> 4) * 4;
    const int sk0 = (tid & 15) * 4;

    __syncthreads();

    for (int kt = 0; kt < 16; ++kt) {
        const int k0i = kt * 64;
        for (int idx = tid; idx < 64*64; idx += 256) {
            int rr = idx >> 6, c = idx & 63;
            size_t g = base + (size_t)(k0i + rr)*QKVW + c;
            k1s[rr*PITCH + c] = qkv[g + 2*NHEADS*HDIM];
            k2s[rr*PITCH + c] = qkv[g + 3*NHEADS*HDIM];
            vs [rr*PITCH + c] = qkv[g + 4*NHEADS*HDIM];
        }
        __syncthreads();

        // ---- scores (4x4 register blocking, both streams) ----
        {
            float acc1[4][4], acc2[4][4];
#pragma unroll
            for (int i = 0; i < 4; i++)
#pragma unroll
                for (int j = 0; j < 4; j++) { acc1[i][j] = 0.f; acc2[i][j] = 0.f; }
            for (int d = 0; d < 64; ++d) {
                float qa1[4], qa2[4], kb1[4], kb2[4];
#pragma unroll
                for (int i = 0; i < 4; i++) {
                    qa1[i] = q1s[(sr0+i)*PITCH + d];
                    qa2[i] = q2s[(sr0+i)*PITCH + d];
                    kb1[i] = k1s[(sk0+i)*PITCH + d];
                    kb2[i] = k2s[(sk0+i)*PITCH + d];
                }
#pragma unroll
                for (int i = 0; i < 4; i++)
#pragma unroll
                    for (int j = 0; j < 4; j++) {
                        acc1[i][j] += qa1[i]*kb1[j];
                        acc2[i][j] += qa2[i]*kb2[j];
                    }
            }
#pragma unroll
            for (int i = 0; i < 4; i++)
#pragma unroll
                for (int j = 0; j < 4; j++) {
                    s1[(sr0+i)*PITCH + sk0+j] =
                        fminf(fmaxf(acc1[i][j]*scale, -ATTN_CLIP), ATTN_CLIP);
                    s2[(sr0+i)*PITCH + sk0+j] =
                        fminf(fmaxf(acc2[i][j]*scale, -ATTN_CLIP), ATTN_CLIP);
                }
        }
        __syncthreads();

        // ---- online softmax update (4 lanes per row cooperate via shfl) ----
        {
            float tm1 = -1e30f, tm2 = -1e30f;
#pragma unroll
            for (int i = 0; i < 16; i++) {
                tm1 = fmaxf(tm1, s1[r*PITCH + kg + i]);
                tm2 = fmaxf(tm2, s2[r*PITCH + kg + i]);
            }
            tm1 = fmaxf(tm1, __shfl_xor_sync(0xffffffffu, tm1, 1));
            tm1 = fmaxf(tm1, __shfl_xor_sync(0xffffffffu, tm1, 2));
            tm2 = fmaxf(tm2, __shfl_xor_sync(0xffffffffu, tm2, 1));
            tm2 = fmaxf(tm2, __shfl_xor_sync(0xffffffffu, tm2, 2));
            float nm1 = fmaxf(m1, tm1), nm2 = fmaxf(m2, tm2);
            float ts1 = 0.f, ts2 = 0.f;
#pragma unroll
            for (int i = 0; i < 16; i++) {
                float p1 = __expf(s1[r*PITCH + kg + i] - nm1);
                s1[r*PITCH + kg + i] = p1; ts1 += p1;
                float p2 = __expf(s2[r*PITCH + kg + i] - nm2);
                s2[r*PITCH + kg + i] = p2; ts2 += p2;
            }
            ts1 += __shfl_xor_sync(0xffffffffu, ts1, 1);
            ts1 += __shfl_xor_sync(0xffffffffu, ts1, 2);
            ts2 += __shfl_xor_sync(0xffffffffu, ts2, 1);
            ts2 += __shfl_xor_sync(0xffffffffu, ts2, 2);
            float c1 = __expf(m1 - nm1), c2 = __expf(m2 - nm2);
            l1 = l1*c1 + ts1;  l2 = l2*c2 + ts2;
#pragma unroll
            for (int j = 0; j < 16; j++) { o1[j] *= c1; o2[j] *= c2; }
            m1 = nm1; m2 = nm2;
        }
        __syncwarp();   // p-writes for row r come from lanes of the same warp

        // ---- AV accumulate ----
#pragma unroll 4
        for (int kk = 0; kk < 64; ++kk) {
            float p1 = s1[r*PITCH + kk], p2 = s2[r*PITCH + kk];
            const float* vrow = &vs[kk*PITCH + dbase];
#pragma unroll
            for (int j = 0; j < 16; j++) {
                float vv = vrow[j];
                o1[j] += p1*vv;
                o2[j] += p2*vv;
            }
        }
        __syncthreads();
    }

    const float inv1 = 1.f / (l1 + EPSF);
    const float inv2 = 1.f / (l2 + EPSF);
    size_t obase = ((size_t)b*SEQ + q0 + r)*DIM + (size_t)h*HDIM + dbase;
#pragma unroll
    for (int j = 0; j < 16; j++)
        o[obase + j] = o1[j]*inv1 - lam*(o2[j]*inv2);
}

// ---------------- launch ----------------
extern "C" void kernel_launch(void* const* d_in, const int* in_sizes, int n_in,
                              void* d_out, int out_size) {
    const float* x      = (const float*)d_in[0];
    const float* w_qkv  = (const float*)d_in[1];
    const float* lq1    = (const float*)d_in[2];
    const float* lk1    = (const float*)d_in[3];
    const float* lq2    = (const float*)d_in[4];
    const float* lk2    = (const float*)d_in[5];
    const float* w_proj = (const float*)d_in[6];
    const float* b_proj = (const float*)d_in[7];
    const float* gamma1 = (const float*)d_in[8];
    const float* beta1  = (const float*)d_in[9];
    const float* gamma2 = (const float*)d_in[10];
    const float* beta2  = (const float*)d_in[11];
    const float* w1     = (const float*)d_in[12];
    const float* b1     = (const float*)d_in[13];
    const float* w2     = (const float*)d_in[14];
    const float* b2     = (const float*)d_in[15];
    float* out = (float*)d_out;

    float *p_h, *p_qkv, *p_o, *p_x2, *p_h2, *p_f;
    cudaGetSymbolAddress((void**)&p_h,   g_h);
    cudaGetSymbolAddress((void**)&p_qkv, g_qkv);
    cudaGetSymbolAddress((void**)&p_o,   g_o);
    cudaGetSymbolAddress((void**)&p_x2,  g_x2);
    cudaGetSymbolAddress((void**)&p_h2,  g_h2);
    cudaGetSymbolAddress((void**)&p_f,   g_f);

    cudaFuncSetAttribute(diff_attn_kernel,
                         cudaFuncAttributeMaxDynamicSharedMemorySize, SMEM_ATTN);

    // scalars
    reduce_sq_kernel<<<dim3(128, BATCH), 256>>>(x);
    compute_nx_kernel<<<1, 32>>>();
    compute_lam_kernel<<<1, 1>>>(lq1, lk1, lq2, lk2);

    // GRN1
    grn_kernel<<<(MTOT*DIM)/4/256, 256>>>(x, gamma1, beta1, p_h);

    // QKV GEMM: (4096 x 1024) @ (1024 x 5120)
    sgemm_kernel<0><<<dim3(QKVW/128, MTOT/128), 256>>>(p_h, w_qkv, p_qkv,
                                                       MTOT, QKVW, DIM, nullptr, nullptr);

    // differential flash attention -> g_o (already (B,S,H*hd))
    diff_attn_kernel<<<dim3(SEQ/64, NHEADS, BATCH), 256, SMEM_ATTN>>>(p_qkv, p_o);

    // proj + bias + residual(x) -> x2
    sgemm_kernel<2><<<dim3(DIM/128, MTOT/128), 256>>>(p_o, w_proj, p_x2,
                                                      MTOT, DIM, DIM, b_proj, x);

    // GRN2
    reduce_sq_kernel<<<dim3(128, BATCH), 256>>>(p_x2);
    compute_nx_kernel<<<1, 32>>>();
    grn_kernel<<<(MTOT*DIM)/4/256, 256>>>(p_x2, gamma2, beta2, p_h2);

    // FFN1: silu(h2 @ w1 + b1)
    sgemm_kernel<3><<<dim3(MLP/128, MTOT/128), 256>>>(p_h2, w1, p_f,
                                                      MTOT, MLP, DIM, b1, nullptr);

    // FFN2: f @ w2 + b2 + residual(x2) -> out
    sgemm_kernel<2><<<dim3(DIM/128, MTOT/128), 256>>>(p_f, w2, out,
                                                      MTOT, DIM, MLP, b2, p_x2);
}

// round 4
// speedup vs baseline: 1.4721x; 1.4721x over previous
#include <cuda_runtime.h>
#include <cuda_bf16.h>
#include <mma.h>
#include <math.h>
#include <cstdint>

using namespace nvcuda;

#define BATCH 4
#define SEQ 1024
#define DIM 1024
#define NHEADS 16
#define HDIM 64
#define MLP 4096
#define MTOT (BATCH*SEQ)        /* 4096 */
#define QKVW (5*NHEADS*HDIM)    /* 5120 */
#define ATTN_CLIP 100.0f
#define NORM_CLIP 1000.0f
#define EPSF 1e-6f

// ================= scratch =================
__device__ float g_h  [MTOT*DIM];
__device__ float g_qkv[MTOT*QKVW];
__device__ float g_o  [MTOT*DIM];
__device__ float g_x2 [MTOT*DIM];
__device__ float g_h2 [MTOT*DIM];
__device__ float g_f  [(size_t)MTOT*MLP];
__device__ __nv_bfloat16 g_ahi[(size_t)MTOT*MLP];   // max M*K = 4096*4096
__device__ __nv_bfloat16 g_alo[(size_t)MTOT*MLP];
__device__ __nv_bfloat16 g_bhi[(size_t)QKVW*DIM];   // max N*K = 5120*1024
__device__ __nv_bfloat16 g_blo[(size_t)QKVW*DIM];
__device__ float g_part[BATCH*128];
__device__ float g_nx[BATCH];
__device__ float g_lam;

// ================= cp.async =================
__device__ __forceinline__ uint32_t smem_u32(const void* p) {
    uint32_t a;
    asm("{ .reg .u64 t; cvta.to.shared.u64 t, %1; cvt.u32.u64 %0, t; }" : "=r"(a) : "l"(p));
    return a;
}
#define CP_ASYNC16(dst, src) \
    asm volatile("cp.async.cg.shared.global [%0], [%1], 16;" :: "r"(dst), "l"(src))
#define CP_COMMIT() asm volatile("cp.async.commit_group;" ::: "memory")
#define CP_WAIT(n)  asm volatile("cp.async.wait_group %0;" :: "n"(n) : "memory")

// ================= scalar / GRN kernels =================
__global__ void reduce_sq_kernel(const float* __restrict__ x) {
    const int b = blockIdx.y, blk = blockIdx.x;
    const int N = SEQ*DIM;
    const int per = N / 128;
    const float* p = x + (size_t)b*N + (size_t)blk*per;
    float s = 0.f;
    for (int i = threadIdx.x; i < per; i += 256) { float v = p[i]; s += v*v; }
    __shared__ float red[8];
    int lane = threadIdx.x & 31, w = threadIdx.x >> 5;
#pragma unroll
    for (int o = 16; o; o >>= 1) s += __shfl_down_sync(0xffffffffu, s, o);
    if (lane == 0) red[w] = s;
    __syncthreads();
    if (w == 0) {
        s = (lane < 8) ? red[lane] : 0.f;
#pragma unroll
        for (int o = 4; o; o >>= 1) s += __shfl_down_sync(0xffffffffu, s, o);
        if (lane == 0) g_part[b*128 + blk] = s;
    }
}

__global__ void compute_nx_kernel() {
    int b = threadIdx.x;
    if (b < BATCH) {
        float s = 0.f;
        for (int i = 0; i < 128; i++) s += g_part[b*128 + i];
        s = fminf(fmaxf(s, EPSF), NORM_CLIP);
        float gx = sqrtf(s);
        float nx = gx / (gx + EPSF);
        nx = fminf(fmaxf(nx, -NORM_CLIP), NORM_CLIP);
        g_nx[b] = nx;
    }
}

__global__ void compute_lam_kernel(const float* __restrict__ lq1, const float* __restrict__ lk1,
                                   const float* __restrict__ lq2, const float* __restrict__ lk2) {
    float s1 = 0.f, s2 = 0.f;
    for (int d = 0; d < HDIM; d++) { s1 += lq1[d]*lk1[d]; s2 += lq2[d]*lk2[d]; }
    s1 = fminf(fmaxf(s1, -10.f), 10.f);
    s2 = fminf(fmaxf(s2, -10.f), 10.f);
    float lam_init = 0.8f - 0.6f*expf(-0.0f);
    float lam = expf(s1) - expf(s2) + lam_init;
    g_lam = fminf(fmaxf(lam, 0.1f), 5.f);
}

__global__ void grn_kernel(const float* __restrict__ x, const float* __restrict__ gamma,
                           const float* __restrict__ beta, float* __restrict__ out) {
    int idx = blockIdx.x*blockDim.x + threadIdx.x;
    int e = idx * 4;
    int b = e / (SEQ*DIM);
    int d = e % DIM;
    float nx = g_nx[b];
    float4 xv = *(const float4*)(x + e);
    float4 gv = *(const float4*)(gamma + d);
    float4 bv = *(const float4*)(beta + d);
    float4 r;
    r.x = gv.x*(xv.x*nx) + bv.x + xv.x;
    r.y = gv.y*(xv.y*nx) + bv.y + xv.y;
    r.z = gv.z*(xv.z*nx) + bv.z + xv.z;
    r.w = gv.w*(xv.w*nx) + bv.w + xv.w;
    *(float4*)(out + e) = r;
}

// ================= fp32 -> bf16 hi/lo split =================
__global__ void split_kernel(const float* __restrict__ x,
                             __nv_bfloat16* __restrict__ hi,
                             __nv_bfloat16* __restrict__ lo) {
    int idx = blockIdx.x*blockDim.x + threadIdx.x;
    int e = idx * 4;
    float4 v = *(const float4*)(x + e);
    __nv_bfloat16 h0 = __float2bfloat16(v.x), h1 = __float2bfloat16(v.y);
    __nv_bfloat16 h2 = __float2bfloat16(v.z), h3 = __float2bfloat16(v.w);
    __nv_bfloat16 l0 = __float2bfloat16(v.x - __bfloat162float(h0));
    __nv_bfloat16 l1 = __float2bfloat16(v.y - __bfloat162float(h1));
    __nv_bfloat16 l2 = __float2bfloat16(v.z - __bfloat162float(h2));
    __nv_bfloat16 l3 = __float2bfloat16(v.w - __bfloat162float(h3));
    __nv_bfloat162 hp0; hp0.x = h0; hp0.y = h1;
    __nv_bfloat162 hp1; hp1.x = h2; hp1.y = h3;
    __nv_bfloat162 lp0; lp0.x = l0; lp0.y = l1;
    __nv_bfloat162 lp1; lp1.x = l2; lp1.y = l3;
    *(__nv_bfloat162*)(hi + e) = hp0; *(__nv_bfloat162*)(hi + e + 2) = hp1;
    *(__nv_bfloat162*)(lo + e) = lp0; *(__nv_bfloat162*)(lo + e + 2) = lp1;
}

// ================= weight transpose + split: w[K][N] -> t[N][K] bf16 hi/lo =================
__global__ void transpose_split_kernel(const float* __restrict__ w,
                                       __nv_bfloat16* __restrict__ thi,
                                       __nv_bfloat16* __restrict__ tlo,
                                       int K, int N) {
    __shared__ float tile[32][33];
    int n0 = blockIdx.x * 32, k0 = blockIdx.y * 32;
    int tx = threadIdx.x, ty = threadIdx.y;   // 32 x 8
#pragma unroll
    for (int i = 0; i < 4; i++)
        tile[ty + i*8][tx] = w[(size_t)(k0 + ty + i*8)*N + n0 + tx];
    __syncthreads();
#pragma unroll
    for (int i = 0; i < 4; i++) {
        float v = tile[tx][ty + i*8];
        __nv_bfloat16 h = __float2bfloat16(v);
        __nv_bfloat16 l = __float2bfloat16(v - __bfloat162float(h));
        size_t o = (size_t)(n0 + ty + i*8)*K + k0 + tx;
        thi[o] = h; tlo[o] = l;
    }
}

// ================= wmma bf16-split GEMM =================
// A: [M][K] bf16 hi/lo (row-major, K contiguous)
// B: [N][K] bf16 hi/lo (i.e. K x N col-major with ld K)
// C: [M][N] fp32.  EPI: 0=none, 2=+bias+residual, 3=silu(+bias)
#define KC 32
#define LDA 40                       /* bf16 elems per tile row (32 + 8 pad) */
#define TILE_ELEMS (128*LDA)         /* 5120 bf16 = 10240 B */
#define BUF_ELEMS (4*TILE_ELEMS)     /* Ahi,Alo,Bhi,Blo = 40 KB */
#define SMEM_WG (2*BUF_ELEMS*2)      /* 80 KB */
#define SLD 132                      /* fp32 stage leading dim */

template<int EPI>
__global__ __launch_bounds__(256, 2)
void wmma_gemm(const __nv_bfloat16* __restrict__ Ahi, const __nv_bfloat16* __restrict__ Alo,
               const __nv_bfloat16* __restrict__ Bhi, const __nv_bfloat16* __restrict__ Blo,
               float* __restrict__ C, int M, int N, int K,
               const float* __restrict__ bias, const float* __restrict__ res) {
    extern __shared__ char smem_raw[];
    __nv_bfloat16* sm = (__nv_bfloat16*)smem_raw;
    const uint32_t sm_addr = smem_u32(sm);

    const int tid = threadIdx.x;
    const int wid = tid >> 5;
    const int row0 = blockIdx.y * 128;
    const int col0 = blockIdx.x * 128;
    const int wr = (wid >> 1) * 32;    // warp row within tile
    const int wc = (wid & 1) * 64;     // warp col within tile

    const __nv_bfloat16* gsrc[4] = {
        Ahi + (size_t)row0*K, Alo + (size_t)row0*K,
        Bhi + (size_t)col0*K, Blo + (size_t)col0*K };

    // per-thread load slots: 8 x 16B units; unit -> arr, row, col
    int u_arr[8], u_row[8], u_col[8];
#pragma unroll
    for (int i = 0; i < 8; i++) {
        int idx = tid + i*256;
        u_arr[i] = idx >> 9;
        int rem = idx & 511;
        u_row[i] = rem >> 2;
        u_col[i] = (rem & 3) * 8;
    }

    auto issue_chunk = [&](int k0, int buf) {
        uint32_t dbase = sm_addr + (uint32_t)buf * (BUF_ELEMS*2);
#pragma unroll
        for (int i = 0; i < 8; i++) {
            const __nv_bfloat16* src = gsrc[u_arr[i]] + (size_t)u_row[i]*K + k0 + u_col[i];
            uint32_t dst = dbase + (uint32_t)(u_arr[i]*TILE_ELEMS + u_row[i]*LDA + u_col[i]) * 2;
            CP_ASYNC16(dst, src);
        }
        CP_COMMIT();
    };

    wmma::fragment<wmma::accumulator, 16, 16, 16, float> acc[2][4];
#pragma unroll
    for (int i = 0; i < 2; i++)
#pragma unroll
        for (int j = 0; j < 4; j++) wmma::fill_fragment(acc[i][j], 0.f);

    const int nch = K / KC;
    issue_chunk(0, 0);

    for (int ch = 0; ch < nch; ch++) {
        const int cur = ch & 1;
        if (ch + 1 < nch) { issue_chunk((ch+1)*KC, cur ^ 1); CP_WAIT(1); }
        else              { CP_WAIT(0); }
        __syncthreads();

        const __nv_bfloat16* b0 = sm + cur * BUF_ELEMS;
        const __nv_bfloat16* tAhi = b0 + 0*TILE_ELEMS + wr*LDA;
        const __nv_bfloat16* tAlo = b0 + 1*TILE_ELEMS + wr*LDA;
        const __nv_bfloat16* tBhi = b0 + 2*TILE_ELEMS + wc*LDA;
        const __nv_bfloat16* tBlo = b0 + 3*TILE_ELEMS + wc*LDA;

#pragma unroll
        for (int ks = 0; ks < 2; ks++) {
            wmma::fragment<wmma::matrix_a, 16, 16, 16, __nv_bfloat16, wmma::row_major> aH[2], aL[2];
            wmma::fragment<wmma::matrix_b, 16, 16, 16, __nv_bfloat16, wmma::col_major> bF[4];
            const int ko = ks * 16;
#pragma unroll
            for (int i = 0; i < 2; i++)
                wmma::load_matrix_sync(aH[i], tAhi + i*16*LDA + ko, LDA);
#pragma unroll
            for (int j = 0; j < 4; j++)
                wmma::load_matrix_sync(bF[j], tBhi + j*16*LDA + ko, LDA);
            // pass hh
#pragma unroll
            for (int i = 0; i < 2; i++)
#pragma unroll
                for (int j = 0; j < 4; j++)
                    wmma::mma_sync(acc[i][j], aH[i], bF[j], acc[i][j]);
            // pass lh (reuse bF = Bhi)
#pragma unroll
            for (int i = 0; i < 2; i++)
                wmma::load_matrix_sync(aL[i], tAlo + i*16*LDA + ko, LDA);
#pragma unroll
            for (int i = 0; i < 2; i++)
#pragma unroll
                for (int j = 0; j < 4; j++)
                    wmma::mma_sync(acc[i][j], aL[i], bF[j], acc[i][j]);
            // pass hl (reuse aH = Ahi)
#pragma unroll
            for (int j = 0; j < 4; j++)
                wmma::load_matrix_sync(bF[j], tBlo + j*16*LDA + ko, LDA);
#pragma unroll
            for (int i = 0; i < 2; i++)
#pragma unroll
                for (int j = 0; j < 4; j++)
                    wmma::mma_sync(acc[i][j], aH[i], bF[j], acc[i][j]);
        }
        __syncthreads();
    }

    // stage fp32 result in smem, then fused epilogue with coalesced stores
    float* stage = (float*)smem_raw;
#pragma unroll
    for (int i = 0; i < 2; i++)
#pragma unroll
        for (int j = 0; j < 4; j++)
            wmma::store_matrix_sync(stage + (wr + i*16)*SLD + wc + j*16,
                                    acc[i][j], SLD, wmma::mem_row_major);
    __syncthreads();

    const int r = tid >> 1;
    const int c0 = (tid & 1) * 64;
    const int row = row0 + r;
    size_t obase = (size_t)row*N + col0 + c0;
#pragma unroll
    for (int j = 0; j < 16; j++) {
        float4 v = *(float4*)(stage + r*SLD + c0 + j*4);
        float4 w;
        float* vi = (float*)&v; float* wi = (float*)&w;
#pragma unroll
        for (int q = 0; q < 4; q++) {
            float t = vi[q];
            if (EPI >= 1) t += bias[col0 + c0 + j*4 + q];
            if (EPI == 3) t = t / (1.f + __expf(-t));
            if (EPI == 2) t += res[obase + j*4 + q];
            wi[q] = t;
        }
        *(float4*)(C + obase + j*4) = w;
    }
}

// ================= fused differential flash attention =================
#define PITCH 65
#define SMEM_ATTN (7 * 64 * PITCH * 4)

__global__ __launch_bounds__(256)
void diff_attn_kernel(const float* __restrict__ qkv, float* __restrict__ o) {
    extern __shared__ float sm[];
    float* q1s = sm;
    float* q2s = q1s + 64*PITCH;
    float* k1s = q2s + 64*PITCH;
    float* k2s = k1s + 64*PITCH;
    float* vs  = k2s + 64*PITCH;
    float* s1  = vs  + 64*PITCH;
    float* s2  = s1  + 64*PITCH;

    const int tid = threadIdx.x;
    const int qt = blockIdx.x, h = blockIdx.y, b = blockIdx.z;
    const int q0 = qt * 64;
    const float scale = 0.125f;
    const float lam = g_lam;

    const size_t base = ((size_t)b*SEQ)*QKVW + (size_t)h*HDIM;

    for (int idx = tid; idx < 64*64; idx += 256) {
        int r = idx >> 6, c = idx & 63;
        size_t g = base + (size_t)(q0 + r)*QKVW + c;
        q1s[r*PITCH + c] = qkv[g + 0*NHEADS*HDIM];
        q2s[r*PITCH + c] = qkv[g + 1*NHEADS*HDIM];
    }

    const int r  = tid >> 2;
    const int kg = (tid & 3) * 16;
    const int dbase = kg;
    float m1 = -1e30f, l1 = 0.f, m2 = -1e30f, l2 = 0.f;
    float o1[16], o2[16];
#pragma unroll
    for (int j = 0; j < 16; j++) { o1[j] = 0.f; o2[j] = 0.f; }

    const int sr0 = (tid >> 4) * 4;
    const int sk0 = (tid & 15) * 4;

    __syncthreads();

    for (int kt = 0; kt < 16; ++kt) {
        const int k0i = kt * 64;
        for (int idx = tid; idx < 64*64; idx += 256) {
            int rr = idx >> 6, c = idx & 63;
            size_t g = base + (size_t)(k0i + rr)*QKVW + c;
            k1s[rr*PITCH + c] = qkv[g + 2*NHEADS*HDIM];
            k2s[rr*PITCH + c] = qkv[g + 3*NHEADS*HDIM];
            vs [rr*PITCH + c] = qkv[g + 4*NHEADS*HDIM];
        }
        __syncthreads();

        {
            float acc1[4][4], acc2[4][4];
#pragma unroll
            for (int i = 0; i < 4; i++)
#pragma unroll
                for (int j = 0; j < 4; j++) { acc1[i][j] = 0.f; acc2[i][j] = 0.f; }
            for (int d = 0; d < 64; ++d) {
                float qa1[4], qa2[4], kb1[4], kb2[4];
#pragma unroll
                for (int i = 0; i < 4; i++) {
                    qa1[i] = q1s[(sr0+i)*PITCH + d];
                    qa2[i] = q2s[(sr0+i)*PITCH + d];
                    kb1[i] = k1s[(sk0+i)*PITCH + d];
                    kb2[i] = k2s[(sk0+i)*PITCH + d];
                }
#pragma unroll
                for (int i = 0; i < 4; i++)
#pragma unroll
                    for (int j = 0; j < 4; j++) {
                        acc1[i][j] += qa1[i]*kb1[j];
                        acc2[i][j] += qa2[i]*kb2[j];
                    }
            }
#pragma unroll
            for (int i = 0; i < 4; i++)
#pragma unroll
                for (int j = 0; j < 4; j++) {
                    s1[(sr0+i)*PITCH + sk0+j] =
                        fminf(fmaxf(acc1[i][j]*scale, -ATTN_CLIP), ATTN_CLIP);
                    s2[(sr0+i)*PITCH + sk0+j] =
                        fminf(fmaxf(acc2[i][j]*scale, -ATTN_CLIP), ATTN_CLIP);
                }
        }
        __syncthreads();

        {
            float tm1 = -1e30f, tm2 = -1e30f;
#pragma unroll
            for (int i = 0; i < 16; i++) {
                tm1 = fmaxf(tm1, s1[r*PITCH + kg + i]);
                tm2 = fmaxf(tm2, s2[r*PITCH + kg + i]);
            }
            tm1 = fmaxf(tm1, __shfl_xor_sync(0xffffffffu, tm1, 1));
            tm1 = fmaxf(tm1, __shfl_xor_sync(0xffffffffu, tm1, 2));
            tm2 = fmaxf(tm2, __shfl_xor_sync(0xffffffffu, tm2, 1));
            tm2 = fmaxf(tm2, __shfl_xor_sync(0xffffffffu, tm2, 2));
            float nm1 = fmaxf(m1, tm1), nm2 = fmaxf(m2, tm2);
            float ts1 = 0.f, ts2 = 0.f;
#pragma unroll
            for (int i = 0; i < 16; i++) {
                float p1 = __expf(s1[r*PITCH + kg + i] - nm1);
                s1[r*PITCH + kg + i] = p1; ts1 += p1;
                float p2 = __expf(s2[r*PITCH + kg + i] - nm2);
                s2[r*PITCH + kg + i] = p2; ts2 += p2;
            }
            ts1 += __shfl_xor_sync(0xffffffffu, ts1, 1);
            ts1 += __shfl_xor_sync(0xffffffffu, ts1, 2);
            ts2 += __shfl_xor_sync(0xffffffffu, ts2, 1);
            ts2 += __shfl_xor_sync(0xffffffffu, ts2, 2);
            float c1 = __expf(m1 - nm1), c2 = __expf(m2 - nm2);
            l1 = l1*c1 + ts1;  l2 = l2*c2 + ts2;
#pragma unroll
            for (int j = 0; j < 16; j++) { o1[j] *= c1; o2[j] *= c2; }
            m1 = nm1; m2 = nm2;
        }
        __syncwarp();

#pragma unroll 4
        for (int kk = 0; kk < 64; ++kk) {
            float p1 = s1[r*PITCH + kk], p2 = s2[r*PITCH + kk];
            const float* vrow = &vs[kk*PITCH + dbase];
#pragma unroll
            for (int j = 0; j < 16; j++) {
                float vv = vrow[j];
                o1[j] += p1*vv;
                o2[j] += p2*vv;
            }
        }
        __syncthreads();
    }

    const float inv1 = 1.f / (l1 + EPSF);
    const float inv2 = 1.f / (l2 + EPSF);
    size_t obase = ((size_t)b*SEQ + q0 + r)*DIM + (size_t)h*HDIM + dbase;
#pragma unroll
    for (int j = 0; j < 16; j++)
        o[obase + j] = o1[j]*inv1 - lam*(o2[j]*inv2);
}

// ================= launch =================
extern "C" void kernel_launch(void* const* d_in, const int* in_sizes, int n_in,
                              void* d_out, int out_size) {
    const float* x      = (const float*)d_in[0];
    const float* w_qkv  = (const float*)d_in[1];
    const float* lq1    = (const float*)d_in[2];
    const float* lk1    = (const float*)d_in[3];
    const float* lq2    = (const float*)d_in[4];
    const float* lk2    = (const float*)d_in[5];
    const float* w_proj = (const float*)d_in[6];
    const float* b_proj = (const float*)d_in[7];
    const float* gamma1 = (const float*)d_in[8];
    const float* beta1  = (const float*)d_in[9];
    const float* gamma2 = (const float*)d_in[10];
    const float* beta2  = (const float*)d_in[11];
    const float* w1     = (const float*)d_in[12];
    const float* b1     = (const float*)d_in[13];
    const float* w2     = (const float*)d_in[14];
    const float* b2     = (const float*)d_in[15];
    float* out = (float*)d_out;

    float *p_h, *p_qkv, *p_o, *p_x2, *p_h2, *p_f;
    __nv_bfloat16 *p_ahi, *p_alo, *p_bhi, *p_blo;
    cudaGetSymbolAddress((void**)&p_h,   g_h);
    cudaGetSymbolAddress((void**)&p_qkv, g_qkv);
    cudaGetSymbolAddress((void**)&p_o,   g_o);
    cudaGetSymbolAddress((void**)&p_x2,  g_x2);
    cudaGetSymbolAddress((void**)&p_h2,  g_h2);
    cudaGetSymbolAddress((void**)&p_f,   g_f);
    cudaGetSymbolAddress((void**)&p_ahi, g_ahi);
    cudaGetSymbolAddress((void**)&p_alo, g_alo);
    cudaGetSymbolAddress((void**)&p_bhi, g_bhi);
    cudaGetSymbolAddress((void**)&p_blo, g_blo);

    cudaFuncSetAttribute(diff_attn_kernel,
                         cudaFuncAttributeMaxDynamicSharedMemorySize, SMEM_ATTN);
    cudaFuncSetAttribute(wmma_gemm<0>, cudaFuncAttributeMaxDynamicSharedMemorySize, SMEM_WG);
    cudaFuncSetAttribute(wmma_gemm<2>, cudaFuncAttributeMaxDynamicSharedMemorySize, SMEM_WG);
    cudaFuncSetAttribute(wmma_gemm<3>, cudaFuncAttributeMaxDynamicSharedMemorySize, SMEM_WG);

    // scalars
    reduce_sq_kernel<<<dim3(128, BATCH), 256>>>(x);
    compute_nx_kernel<<<1, 32>>>();
    compute_lam_kernel<<<1, 1>>>(lq1, lk1, lq2, lk2);

    // GRN1 -> h
    grn_kernel<<<(MTOT*DIM)/4/256, 256>>>(x, gamma1, beta1, p_h);

    // QKV GEMM: h(4096x1024) @ w_qkv(1024x5120)
    split_kernel<<<(MTOT*DIM)/4/256, 256>>>(p_h, p_ahi, p_alo);
    transpose_split_kernel<<<dim3(QKVW/32, DIM/32), dim3(32, 8)>>>(w_qkv, p_bhi, p_blo, DIM, QKVW);
    wmma_gemm<0><<<dim3(QKVW/128, MTOT/128), 256, SMEM_WG>>>(
        p_ahi, p_alo, p_bhi, p_blo, p_qkv, MTOT, QKVW, DIM, nullptr, nullptr);

    // differential flash attention -> o (B,S,H*hd)
    diff_attn_kernel<<<dim3(SEQ/64, NHEADS, BATCH), 256, SMEM_ATTN>>>(p_qkv, p_o);

    // proj + bias + residual(x) -> x2
    split_kernel<<<(MTOT*DIM)/4/256, 256>>>(p_o, p_ahi, p_alo);
    transpose_split_kernel<<<dim3(DIM/32, DIM/32), dim3(32, 8)>>>(w_proj, p_bhi, p_blo, DIM, DIM);
    wmma_gemm<2><<<dim3(DIM/128, MTOT/128), 256, SMEM_WG>>>(
        p_ahi, p_alo, p_bhi, p_blo, p_x2, MTOT, DIM, DIM, b_proj, x);

    // GRN2 -> h2
    reduce_sq_kernel<<<dim3(128, BATCH), 256>>>(p_x2);
    compute_nx_kernel<<<1, 32>>>();
    grn_kernel<<<(MTOT*DIM)/4/256, 256>>>(p_x2, gamma2, beta2, p_h2);

    // FFN1: silu(h2 @ w1 + b1) -> f
    split_kernel<<<(MTOT*DIM)/4/256, 256>>>(p_h2, p_ahi, p_alo);
    transpose_split_kernel<<<dim3(MLP/32, DIM/32), dim3(32, 8)>>>(w1, p_bhi, p_blo, DIM, MLP);
    wmma_gemm<3><<<dim3(MLP/128, MTOT/128), 256, SMEM_WG>>>(
        p_ahi, p_alo, p_bhi, p_blo, p_f, MTOT, MLP, DIM, b1, nullptr);

    // FFN2: f @ w2 + b2 + residual(x2) -> out
    split_kernel<<<((size_t)MTOT*MLP)/4/256, 256>>>(p_f, p_ahi, p_alo);
    transpose_split_kernel<<<dim3(DIM/32, MLP/32), dim3(32, 8)>>>(w2, p_bhi, p_blo, MLP, DIM);
    wmma_gemm<2><<<dim3(DIM/128, MTOT/128), 256, SMEM_WG>>>(
        p_ahi, p_alo, p_bhi, p_blo, out, MTOT, DIM, MLP, b2, p_x2);
}